// round 16
// baseline (speedup 1.0000x reference)
#include <cuda_runtime.h>
#include <math.h>

#define BB   64
#define HW   4096
#define CC   64
#define NH   4
#define CF   64
#define BD   16
#define FIN  80      // C + BASIS_DIM
#define CP   128     // positions per chunk
#define NCH  32      // chunks per batch
#define KSL  32      // k1a: K slices of 32

typedef unsigned long long ull;

// ---------------- scratch (device globals) ---------------------------------
__device__ float  g_qp[KSL * BB * CF];       // k1a partials [slice][b][j]
__device__ float  g_wq[BB * FIN * NH];       // [b][c][n]
__device__ float  g_sbias[BB * NH];
__device__ ull    g_wu[BB * HW * 2];         // exp(s) per head, packed 2 heads / ull
__device__ float  g_fsum[BB * FIN * NH];     // atomically accumulated weighted features
__device__ float  g_Lsum[BB * NH];           // atomically accumulated exp sums

// ---------------- PTX helpers ----------------------------------------------
__device__ __forceinline__ void ldsv2(ull &a, ull &b, unsigned int addr) {
    asm("ld.shared.v2.u64 {%0,%1}, [%2];" : "=l"(a), "=l"(b) : "r"(addr));
}
__device__ __forceinline__ void ldsv2f(float &a, float &b, unsigned int addr) {
    asm("ld.shared.v2.f32 {%0,%1}, [%2];" : "=f"(a), "=f"(b) : "r"(addr));
}
__device__ __forceinline__ void fma2(ull &d, ull a, ull b) {
    asm("fma.rn.f32x2 %0, %1, %2, %0;" : "+l"(d) : "l"(a), "l"(b));
}
__device__ __forceinline__ ull pk2(float f) {
    ull d; unsigned int u = __float_as_uint(f);
    asm("mov.b64 %0, {%1, %1};" : "=l"(d) : "r"(u));
    return d;
}
__device__ __forceinline__ ull pack2(float lo, float hi) {
    ull d;
    asm("mov.b64 %0, {%1, %2};" : "=l"(d) : "r"(__float_as_uint(lo)), "r"(__float_as_uint(hi)));
    return d;
}
__device__ __forceinline__ void unpk(float &lo, float &hi, ull v) {
    unsigned int a, b;
    asm("mov.b64 {%0,%1}, %2;" : "=r"(a), "=r"(b) : "l"(v));
    lo = __uint_as_float(a); hi = __uint_as_float(b);
}
__device__ __forceinline__ void stsu64(unsigned int addr, ull v) {
    asm volatile("st.shared.u64 [%0], %1;" :: "r"(addr), "l"(v));
}
__device__ __forceinline__ void cpasync16(unsigned int saddr, const void *gaddr) {
    asm volatile("cp.async.cg.shared.global [%0], [%1], 16;" :: "r"(saddr), "l"(gaddr));
}

// ---------------- K1a: K-sliced GEMM + zero the atomic accumulators --------
__global__ void __launch_bounds__(256)
k1a_gemm(const float* __restrict__ s1, const float* __restrict__ s2,
         const float* __restrict__ Wq) {
    int ks = blockIdx.x;            // 32 slices, 32 k each
    int t  = threadIdx.x;           // 256 threads
    __shared__ float ssh[BB * 33];  // state[b][kk], padded
    __shared__ float wsh[32 * CF];  // Wq[kk][j]

    // zero atomic accumulators (k1a completes before k2 launches: stream order)
    int gid = ks * 256 + t;         // 8192 threads
    #pragma unroll
    for (int r = 0; r < 3; r++) {
        int idx = gid + r * 8192;
        if (idx < BB * FIN * NH) g_fsum[idx] = 0.f;
    }
    if (gid < BB * NH) g_Lsum[gid] = 0.f;

    int k0 = ks * 32;
    #pragma unroll
    for (int r = 0; r < 8; r++) {
        int idx = t + r * 256;      // 2048 = 64b x 32k
        int bb = idx >> 5, kk = idx & 31;
        int kg = k0 + kk;
        float v = (kg < 512) ? s1[bb * 512 + kg] : s2[bb * 512 + (kg - 512)];
        ssh[bb * 33 + kk] = v;
    }
    #pragma unroll
    for (int r = 0; r < 8; r++) {
        int idx = t + r * 256;      // 2048 = 32k x 64j
        wsh[idx] = Wq[(k0 + (idx >> 6)) * CF + (idx & 63)];
    }
    __syncthreads();

    int j = t & 63, bg = t >> 6;    // each thread: 16 batches x column j
    float acc[16];
    #pragma unroll
    for (int i = 0; i < 16; i++) acc[i] = 0.f;
    #pragma unroll 4
    for (int kk = 0; kk < 32; kk++) {
        float wv = wsh[kk * CF + j];
        const float* sp = ssh + (bg * 16) * 33 + kk;
        #pragma unroll
        for (int i = 0; i < 16; i++) acc[i] += sp[i * 33] * wv;
    }
    #pragma unroll
    for (int i = 0; i < 16; i++)
        g_qp[(ks * BB + bg * 16 + i) * CF + j] = acc[i];
}

// ---------------- K1b: reduce partials; effective queries ------------------
__global__ void k1b_query(const float* __restrict__ bq,
                          const float* __restrict__ Wk, const float* __restrict__ bk) {
    int b = blockIdx.x;
    int t = threadIdx.x;            // 512 threads
    __shared__ float part[8][CF];
    __shared__ float qsh[CF];

    int j = t & 63, g = t >> 6;     // 8 groups x 4 slices
    float a = 0.f;
    #pragma unroll
    for (int s = 0; s < 4; s++)
        a += g_qp[((g * 4 + s) * BB + b) * CF + j];
    part[g][j] = a;
    __syncthreads();
    if (t < CF) {
        float s = bq[t];
        #pragma unroll
        for (int gg = 0; gg < 8; gg++) s += part[gg][t];
        qsh[t] = s;
    }
    __syncthreads();

    if (t < FIN * NH) {
        int c = t >> 2, n = t & 3;
        float acc = 0.f;
        #pragma unroll
        for (int d = 0; d < 16; d++) acc += Wk[c * CF + n * 16 + d] * qsh[n * 16 + d];
        g_wq[b * FIN * NH + t] = acc;
    }
    if (t < NH) {
        float acc = 0.f;
        #pragma unroll
        for (int d = 0; d < 16; d++) acc += bk[t * 16 + d] * qsh[t * 16 + d];
        g_sbias[b * NH + t] = acc;
    }
}

// ---------------- K2 smem layout (bytes) ------------------------------------
//   img  f4[2048] : 0     .. 32768   swizzle c4 ^ (p&15)
//   bas  f4[512]  : 32768 .. 40960   swizzle c4 ^ (p&3)
//   w4   f4[128]  : 40960 .. 43008   (w0,w1,w2,w3) per position
//   wqp  ull[160] : 43008 .. 44288   [c2][n]   (reused as merge float4[80] in B)
//   bias [4]      : 44288 ; red[16] : 44304
#define K2_SMEM_BYTES 44368

__global__ void __launch_bounds__(256, 5)
k2_main(const float* __restrict__ image, const float* __restrict__ basis) {
    extern __shared__ float smem[];
    unsigned int sbase = (unsigned int)__cvta_generic_to_shared(smem);
    const unsigned int w4b = sbase + 40960;
    const unsigned int wqb = sbase + 43008;

    int b  = blockIdx.x;
    int ch = blockIdx.y;
    int t  = threadIdx.x;           // 256 threads
    int p0 = ch * CP;

    float* bias = smem + 11072;     // byte 44288
    float* red  = smem + 11076;

    // ---- async stage image + basis with 16B swizzle ----
    const float4* imb4 = (const float4*)(image + ((long)b * HW + p0) * CC);
    #pragma unroll
    for (int k = 0; k < 8; k++) {
        int idx4 = t + k * 256;
        int p = idx4 >> 4, c4 = idx4 & 15;
        cpasync16(sbase + ((p * 16 + (c4 ^ (p & 15))) << 4), imb4 + idx4);
    }
    const float4* bs4 = (const float4*)(basis + (long)p0 * BD);
    #pragma unroll
    for (int k = 0; k < 2; k++) {
        int idx4 = t + k * 256;
        int p = idx4 >> 2, c4 = idx4 & 3;
        cpasync16(sbase + ((2048 + p * 4 + (c4 ^ (p & 3))) << 4), bs4 + idx4);
    }
    asm volatile("cp.async.commit_group;");

    // ---- meanwhile: wq into interleaved channel-pair layout ----
    #pragma unroll
    for (int k = 0; k < 2; k++) {
        int i = t + k * 256;
        if (i < FIN * NH) {
            int c = i >> 2, n = i & 3;
            smem[10752 + (c >> 1) * 8 + n * 2 + (c & 1)] = g_wq[b * FIN * NH + i];
        }
    }
    if (t < 4) bias[t] = g_sbias[b * NH + t];

    asm volatile("cp.async.wait_group 0;" ::: "memory");
    __syncthreads();

    // ---- phase A: thread = (position-pair, head-pair); 128 active ----
    int pi = t & 63;
    int hp = t >> 6;                // valid for t<128: 0 -> heads 0,1 ; 1 -> heads 2,3
    if (t < 128) {
        ull a0 = 0, a1 = 0, b0 = 0, b1 = 0;   // pos pi heads(hp), pos pi+64 heads(hp)
        int px = pi & 15;                     // (pi+64)&15 == px
        unsigned int qh = wqb + hp * 16;
        #pragma unroll
        for (int g = 0; g < 16; g++) {
            ull fa, fb, fa2, fb2, q0, q1, q2, q3;
            ldsv2(q0, q1, qh + g * 64);
            ldsv2(q2, q3, qh + g * 64 + 32);
            ldsv2(fa, fb, sbase + ((pi * 16 + (g ^ px)) << 4));
            fma2(a0, fa, q0); fma2(a1, fa, q1);
            fma2(a0, fb, q2); fma2(a1, fb, q3);
            ldsv2(fa2, fb2, sbase + (((pi + 64) * 16 + (g ^ px)) << 4));
            fma2(b0, fa2, q0); fma2(b1, fa2, q1);
            fma2(b0, fb2, q2); fma2(b1, fb2, q3);
        }
        int px3 = pi & 3;                     // (pi+64)&3 == px3
        #pragma unroll
        for (int g = 0; g < 4; g++) {
            ull fa, fb, fa2, fb2, q0, q1, q2, q3;
            ldsv2(q0, q1, qh + 1024 + g * 64);
            ldsv2(q2, q3, qh + 1024 + g * 64 + 32);
            ldsv2(fa, fb, sbase + ((2048 + pi * 4 + (g ^ px3)) << 4));
            fma2(a0, fa, q0); fma2(a1, fa, q1);
            fma2(a0, fb, q2); fma2(a1, fb, q3);
            ldsv2(fa2, fb2, sbase + ((2048 + (pi + 64) * 4 + (g ^ px3)) << 4));
            fma2(b0, fa2, q0); fma2(b1, fa2, q1);
            fma2(b0, fb2, q2); fma2(b1, fb2, q3);
        }
        float w0, w1, w2, w3;
        {
            float lo, hi;
            float bs0 = bias[2 * hp + 0], bs1 = bias[2 * hp + 1];
            unpk(lo, hi, a0); w0 = __expf(bs0 + lo + hi);
            unpk(lo, hi, a1); w1 = __expf(bs1 + lo + hi);
            unpk(lo, hi, b0); w2 = __expf(bs0 + lo + hi);
            unpk(lo, hi, b1); w3 = __expf(bs1 + lo + hi);
        }
        ull wpkA = pack2(w0, w1), wpkB = pack2(w2, w3);
        stsu64(w4b + pi * 16 + hp * 8, wpkA);
        stsu64(w4b + (pi + 64) * 16 + hp * 8, wpkB);
        g_wu[((long)b * HW + p0 + pi) * 2 + hp] = wpkA;
        g_wu[((long)b * HW + p0 + pi + 64) * 2 + hp] = wpkB;

        // partial L: sum over this thread's 2 positions, warp-reduce
        float v0 = w0 + w2, v1 = w1 + w3;
        #pragma unroll
        for (int o = 16; o; o >>= 1) {
            v0 += __shfl_xor_sync(0xffffffffu, v0, o);
            v1 += __shfl_xor_sync(0xffffffffu, v1, o);
        }
        int warp = t >> 5, lane = t & 31;
        if (lane == 0) { red[warp * 2 + 0] = v0; red[warp * 2 + 1] = v1; }
    }
    __syncthreads();                // w4 + red visible
    if (t < 4) {
        int h2 = t >> 1, sub = t & 1;     // warps 0,1 -> heads 0,1 ; warps 2,3 -> heads 2,3
        float L = red[(h2 * 2 + 0) * 2 + sub] + red[(h2 * 2 + 1) * 2 + sub];
        atomicAdd(&g_Lsum[b * NH + 2 * h2 + sub], L);
    }

    // ---- phase B: thread = (channel-pair, position-half); 80 active ----
    ull A00 = 0, A01 = 0, A10 = 0, A11 = 0;   // ch c0: h01,h23 ; ch c0+1: h01,h23
    int ch2 = -1;
    if (t < 80) {
        int half = (t >= 40);
        ch2 = half ? t - 40 : t;
        int c0 = ch2 * 2;
        int pb = half << 6;
        if (ch2 < 32) {
            #pragma unroll 4
            for (int j = 0; j < 64; j++) {
                int pp = pb + j;
                float f0, f1;
                ldsv2f(f0, f1, sbase + ((pp * 64 + (c0 ^ ((pp & 15) << 2))) << 2));
                ull w01, w23; ldsv2(w01, w23, w4b + pp * 16);
                ull ff0 = pk2(f0), ff1 = pk2(f1);
                fma2(A00, ff0, w01); fma2(A01, ff0, w23);
                fma2(A10, ff1, w01); fma2(A11, ff1, w23);
            }
        } else {
            int cb = c0 - 64;
            #pragma unroll 4
            for (int j = 0; j < 64; j++) {
                int pp = pb + j;
                float f0, f1;
                ldsv2f(f0, f1, sbase + ((8192 + pp * 16 + (cb ^ ((pp & 3) << 2))) << 2));
                ull w01, w23; ldsv2(w01, w23, w4b + pp * 16);
                ull ff0 = pk2(f0), ff1 = pk2(f1);
                fma2(A00, ff0, w01); fma2(A01, ff0, w23);
                fma2(A10, ff1, w01); fma2(A11, ff1, w23);
            }
        }
        if (half) {     // upper position-half writes partials into merge area
            float x0, x1, x2, x3;
            unpk(x0, x1, A00); unpk(x2, x3, A01);
            ((float4*)(smem + 10752))[c0] = make_float4(x0, x1, x2, x3);
            unpk(x0, x1, A10); unpk(x2, x3, A11);
            ((float4*)(smem + 10752))[c0 + 1] = make_float4(x0, x1, x2, x3);
        }
    }
    __syncthreads();
    if (t < 40) {       // lower half merges + atomically accumulates
        int c0 = ch2 * 2;
        float x0, x1, x2, x3;
        float4 m0 = ((float4*)(smem + 10752))[c0];
        float4 m1 = ((float4*)(smem + 10752))[c0 + 1];
        unpk(x0, x1, A00); unpk(x2, x3, A01);
        float* d0 = &g_fsum[(b * FIN + c0) * NH];
        atomicAdd(d0 + 0, x0 + m0.x);
        atomicAdd(d0 + 1, x1 + m0.y);
        atomicAdd(d0 + 2, x2 + m0.z);
        atomicAdd(d0 + 3, x3 + m0.w);
        unpk(x0, x1, A10); unpk(x2, x3, A11);
        float* d1 = &g_fsum[(b * FIN + c0 + 1) * NH];
        atomicAdd(d1 + 0, x0 + m1.x);
        atomicAdd(d1 + 1, x1 + m1.y);
        atomicAdd(d1 + 2, x2 + m1.z);
        atomicAdd(d1 + 3, x3 + m1.w);
    }
}

// ---------------- K6: fused epilogue ---------------------------------------
// grid (BB, 9), 256 threads. Cheap per-CTA prologue: linv = 1/g_Lsum (4 loads).
// slice 0: Wv via cp.async + 4-way split GEMV + extra copy.
// slices 1..8: mean_attn stream, 512 positions each.
__global__ void __launch_bounds__(256)
k6_out(const float* __restrict__ Wv, const float* __restrict__ bv,
       const float* __restrict__ extra, float* __restrict__ out,
       float* __restrict__ out_ma) {
    int b = blockIdx.x;
    int slice = blockIdx.y;
    int t = threadIdx.x;            // 256 threads
    __shared__ float linv[NH];
    __shared__ float wvsh[FIN * CF];      // 20 KB
    __shared__ float4 fbar4[FIN];
    __shared__ float parts[4][CF];

    if (t < NH) linv[t] = 1.0f / g_Lsum[b * NH + t];

    if (slice == 0) {
        // stage Wv (20 KB) async, coalesced; overlap with fsum + extra loads
        unsigned int wvb = (unsigned int)__cvta_generic_to_shared(wvsh);
        const float4* Wv4 = (const float4*)Wv;
        #pragma unroll
        for (int k = 0; k < 5; k++)
            cpasync16(wvb + (t + k * 256) * 16, Wv4 + t + k * 256);
        asm volatile("cp.async.commit_group;");

        float4 fs = make_float4(0.f, 0.f, 0.f, 0.f);
        if (t < FIN) fs = ((const float4*)g_fsum)[b * FIN + t];
        out[b * 320 + 64 + t] = extra[b * 256 + t];

        asm volatile("cp.async.wait_group 0;" ::: "memory");
        __syncthreads();

        if (t < FIN) {
            fs.x *= linv[0]; fs.y *= linv[1]; fs.z *= linv[2]; fs.w *= linv[3];
            fbar4[t] = fs;
        }
        __syncthreads();

        // 4-way split GEMV: j = output column, g = channel group of 20
        int j = t & 63, g = t >> 6;
        float acc = 0.f;
        #pragma unroll
        for (int cc = 0; cc < 20; cc++) {
            int c = g * 20 + cc;
            acc += wvsh[c * CF + j] * ((const float*)&fbar4[c])[j >> 4];
        }
        parts[g][j] = acc;
        __syncthreads();
        if (t < CF)
            out[b * 320 + t] = bv[t] + parts[0][t] + parts[1][t] + parts[2][t] + parts[3][t];
    } else {
        __syncthreads();            // linv visible
        int p = (slice - 1) * 512 + t * 2;
        const float4* wf = (const float4*)g_wu;
        float4 w0 = wf[b * HW + p];
        float4 w1 = wf[b * HW + p + 1];
        float l0 = linv[0], l1 = linv[1], l2 = linv[2], l3 = linv[3];
        float v0 = 0.25f * (w0.x * l0 + w0.y * l1 + w0.z * l2 + w0.w * l3);
        float v1 = 0.25f * (w1.x * l0 + w1.y * l1 + w1.z * l2 + w1.w * l3);
        *(float2*)(out_ma + b * HW + p) = make_float2(v0, v1);
    }
}

// ---------------- launch ---------------------------------------------------
extern "C" void kernel_launch(void* const* d_in, const int* in_sizes, int n_in,
                              void* d_out, int out_size) {
    (void)in_sizes; (void)n_in; (void)out_size;
    const float* image = (const float*)d_in[0];
    const float* s1    = (const float*)d_in[1];
    const float* s2    = (const float*)d_in[2];
    const float* extra = (const float*)d_in[3];
    const float* Wq    = (const float*)d_in[4];
    const float* bq    = (const float*)d_in[5];
    const float* Wk    = (const float*)d_in[6];
    const float* bk    = (const float*)d_in[7];
    const float* Wv    = (const float*)d_in[8];
    const float* bv    = (const float*)d_in[9];
    const float* basis = (const float*)d_in[10];

    float* out    = (float*)d_out;                 // [B,320]
    float* out_ma = out + BB * 320;                // [B,64,64]

    cudaFuncSetAttribute(k2_main, cudaFuncAttributeMaxDynamicSharedMemorySize, K2_SMEM_BYTES);

    k1a_gemm<<<KSL, 256>>>(s1, s2, Wq);
    k1b_query<<<BB, 512>>>(bq, Wk, bk);
    k2_main<<<dim3(BB, NCH), 256, K2_SMEM_BYTES>>>(image, basis);
    k6_out<<<dim3(BB, 9), 256>>>(Wv, bv, extra, out, out_ma);
}

// round 17
// speedup vs baseline: 1.0567x; 1.0567x over previous
#include <cuda_runtime.h>
#include <math.h>

#define BB   64
#define HW   4096
#define CC   64
#define NH   4
#define CF   64
#define BD   16
#define FIN  80      // C + BASIS_DIM
#define CP   128     // positions per chunk
#define NCH  32      // chunks per batch
#define KSL  32      // k1a: K slices of 32

typedef unsigned long long ull;

// ---------------- scratch (device globals) ---------------------------------
__device__ float  g_qp[KSL * BB * CF];       // k1a partials [slice][b][j]
__device__ float  g_wq[BB * FIN * NH];       // [b][c][n]
__device__ float  g_sbias[BB * NH];
__device__ ull    g_wu[BB * HW * 2];         // exp(s) per head, packed 2 heads / ull
__device__ float  g_fsum[BB * FIN * NH];     // atomically accumulated weighted features
__device__ float  g_Lsum[BB * NH];           // atomically accumulated exp sums

// ---------------- PTX helpers ----------------------------------------------
__device__ __forceinline__ void ldsv2(ull &a, ull &b, unsigned int addr) {
    asm("ld.shared.v2.u64 {%0,%1}, [%2];" : "=l"(a), "=l"(b) : "r"(addr));
}
__device__ __forceinline__ void fma2(ull &d, ull a, ull b) {
    asm("fma.rn.f32x2 %0, %1, %2, %0;" : "+l"(d) : "l"(a), "l"(b));
}
__device__ __forceinline__ ull pk2(float f) {
    ull d; unsigned int u = __float_as_uint(f);
    asm("mov.b64 %0, {%1, %1};" : "=l"(d) : "r"(u));
    return d;
}
__device__ __forceinline__ ull pack2(float lo, float hi) {
    ull d;
    asm("mov.b64 %0, {%1, %2};" : "=l"(d) : "r"(__float_as_uint(lo)), "r"(__float_as_uint(hi)));
    return d;
}
__device__ __forceinline__ void unpk(float &lo, float &hi, ull v) {
    unsigned int a, b;
    asm("mov.b64 {%0,%1}, %2;" : "=r"(a), "=r"(b) : "l"(v));
    lo = __uint_as_float(a); hi = __uint_as_float(b);
}
__device__ __forceinline__ void stsu64(unsigned int addr, ull v) {
    asm volatile("st.shared.u64 [%0], %1;" :: "r"(addr), "l"(v));
}
__device__ __forceinline__ void cpasync16(unsigned int saddr, const void *gaddr) {
    asm volatile("cp.async.cg.shared.global [%0], [%1], 16;" :: "r"(saddr), "l"(gaddr));
}

// ---------------- K1a: K-sliced GEMM + zero the atomic accumulators --------
__global__ void __launch_bounds__(256)
k1a_gemm(const float* __restrict__ s1, const float* __restrict__ s2,
         const float* __restrict__ Wq) {
    int ks = blockIdx.x;            // 32 slices, 32 k each
    int t  = threadIdx.x;           // 256 threads
    __shared__ float ssh[BB * 33];  // state[b][kk], padded
    __shared__ float wsh[32 * CF];  // Wq[kk][j]

    // zero atomic accumulators (k1a completes before k2's gridsync releases)
    int gid = ks * 256 + t;         // 8192 threads
    #pragma unroll
    for (int r = 0; r < 3; r++) {
        int idx = gid + r * 8192;
        if (idx < BB * FIN * NH) g_fsum[idx] = 0.f;
    }
    if (gid < BB * NH) g_Lsum[gid] = 0.f;

    int k0 = ks * 32;
    #pragma unroll
    for (int r = 0; r < 8; r++) {
        int idx = t + r * 256;      // 2048 = 64b x 32k
        int bb = idx >> 5, kk = idx & 31;
        int kg = k0 + kk;
        float v = (kg < 512) ? s1[bb * 512 + kg] : s2[bb * 512 + (kg - 512)];
        ssh[bb * 33 + kk] = v;
    }
    #pragma unroll
    for (int r = 0; r < 8; r++) {
        int idx = t + r * 256;      // 2048 = 32k x 64j
        wsh[idx] = Wq[(k0 + (idx >> 6)) * CF + (idx & 63)];
    }
    __syncthreads();

    int j = t & 63, bg = t >> 6;    // each thread: 16 batches x column j
    float acc[16];
    #pragma unroll
    for (int i = 0; i < 16; i++) acc[i] = 0.f;
    #pragma unroll 4
    for (int kk = 0; kk < 32; kk++) {
        float wv = wsh[kk * CF + j];
        const float* sp = ssh + (bg * 16) * 33 + kk;
        #pragma unroll
        for (int i = 0; i < 16; i++) acc[i] += sp[i * 33] * wv;
    }
    #pragma unroll
    for (int i = 0; i < 16; i++)
        g_qp[(ks * BB + bg * 16 + i) * CF + j] = acc[i];
}

// ---------------- K1b: reduce partials; effective queries ------------------
__global__ void k1b_query(const float* __restrict__ bq,
                          const float* __restrict__ Wk, const float* __restrict__ bk) {
    cudaGridDependencySynchronize();     // PDL: launched early, wait k1a here
    int b = blockIdx.x;
    int t = threadIdx.x;            // 512 threads
    __shared__ float part[8][CF];
    __shared__ float qsh[CF];

    int j = t & 63, g = t >> 6;     // 8 groups x 4 slices
    float a = 0.f;
    #pragma unroll
    for (int s = 0; s < 4; s++)
        a += g_qp[((g * 4 + s) * BB + b) * CF + j];
    part[g][j] = a;
    __syncthreads();
    if (t < CF) {
        float s = bq[t];
        #pragma unroll
        for (int gg = 0; gg < 8; gg++) s += part[gg][t];
        qsh[t] = s;
    }
    __syncthreads();

    if (t < FIN * NH) {
        int c = t >> 2, n = t & 3;
        float acc = 0.f;
        #pragma unroll
        for (int d = 0; d < 16; d++) acc += Wk[c * CF + n * 16 + d] * qsh[n * 16 + d];
        g_wq[b * FIN * NH + t] = acc;
    }
    if (t < NH) {
        float acc = 0.f;
        #pragma unroll
        for (int d = 0; d < 16; d++) acc += bk[t * 16 + d] * qsh[t * 16 + d];
        g_sbias[b * NH + t] = acc;
    }
}

// ---------------- K2 smem layout (bytes) ------------------------------------
//   img  f4[2048] : 0     .. 32768   swizzle c4 ^ (p&15)
//   bas  f4[512]  : 32768 .. 40960   swizzle c4 ^ (p&3)
//   w4   f4[128]  : 40960 .. 43008   (w0,w1,w2,w3) per position
//   wqp  ull[160] : 43008 .. 44288   [c2][n]   (reused as merge float4[80] in B)
//   bias [4]      : 44288 ; red[16] : 44304
#define K2_SMEM_BYTES 44368

__global__ void __launch_bounds__(256, 5)
k2_main(const float* __restrict__ image, const float* __restrict__ basis) {
    extern __shared__ float smem[];
    unsigned int sbase = (unsigned int)__cvta_generic_to_shared(smem);
    const unsigned int w4b = sbase + 40960;
    const unsigned int wqb = sbase + 43008;

    int b  = blockIdx.x;
    int ch = blockIdx.y;
    int t  = threadIdx.x;           // 256 threads
    int p0 = ch * CP;

    float* bias = smem + 11072;     // byte 44288
    float* red  = smem + 11076;

    // ---- async stage image + basis with 16B swizzle (independent of k1) ----
    const float4* imb4 = (const float4*)(image + ((long)b * HW + p0) * CC);
    #pragma unroll
    for (int k = 0; k < 8; k++) {
        int idx4 = t + k * 256;
        int p = idx4 >> 4, c4 = idx4 & 15;
        cpasync16(sbase + ((p * 16 + (c4 ^ (p & 15))) << 4), imb4 + idx4);
    }
    const float4* bs4 = (const float4*)(basis + (long)p0 * BD);
    #pragma unroll
    for (int k = 0; k < 2; k++) {
        int idx4 = t + k * 256;
        int p = idx4 >> 2, c4 = idx4 & 3;
        cpasync16(sbase + ((2048 + p * 4 + (c4 ^ (p & 3))) << 4), bs4 + idx4);
    }
    asm volatile("cp.async.commit_group;");

    // PDL: DRAM staging above overlaps k1b; wait before touching g_wq/g_sbias
    cudaGridDependencySynchronize();

    // ---- wq into interleaved channel-pair layout ----
    #pragma unroll
    for (int k = 0; k < 2; k++) {
        int i = t + k * 256;
        if (i < FIN * NH) {
            int c = i >> 2, n = i & 3;
            smem[10752 + (c >> 1) * 8 + n * 2 + (c & 1)] = g_wq[b * FIN * NH + i];
        }
    }
    if (t < 4) bias[t] = g_sbias[b * NH + t];

    asm volatile("cp.async.wait_group 0;" ::: "memory");
    __syncthreads();

    // ---- phase A: thread = (position, head-pair) ----
    int p  = t & 127;
    int hp = t >> 7;                // 0: heads 0,1 ; 1: heads 2,3
    ull a0 = 0, a1 = 0;
    {
        int px = p & 15;
        unsigned int qh = wqb + hp * 16;
        #pragma unroll
        for (int g = 0; g < 16; g++) {
            ull fa, fb, q0, q1, q2, q3;
            ldsv2(fa, fb, sbase + ((p * 16 + (g ^ px)) << 4));      // channels 4g..4g+3
            ldsv2(q0, q1, qh + g * 64);                             // c2=2g
            ldsv2(q2, q3, qh + g * 64 + 32);                        // c2=2g+1
            fma2(a0, fa, q0); fma2(a1, fa, q1);
            fma2(a0, fb, q2); fma2(a1, fb, q3);
        }
        int px3 = p & 3;
        #pragma unroll
        for (int g = 0; g < 4; g++) {
            ull fa, fb, q0, q1, q2, q3;
            ldsv2(fa, fb, sbase + ((2048 + p * 4 + (g ^ px3)) << 4)); // ch 64+4g..
            ldsv2(q0, q1, qh + 1024 + g * 64);
            ldsv2(q2, q3, qh + 1024 + g * 64 + 32);
            fma2(a0, fa, q0); fma2(a1, fa, q1);
            fma2(a0, fb, q2); fma2(a1, fb, q3);
        }
    }
    float w0, w1;
    {
        float lo, hi, sc0, sc1;
        unpk(lo, hi, a0); sc0 = bias[2 * hp + 0] + lo + hi;
        unpk(lo, hi, a1); sc1 = bias[2 * hp + 1] + lo + hi;
        w0 = __expf(sc0);           // no max subtraction: scores are O(±20), safe in fp32
        w1 = __expf(sc1);
    }
    ull wpk = pack2(w0, w1);
    stsu64(w4b + p * 16 + hp * 8, wpk);
    g_wu[((long)b * HW + p0 + p) * 2 + hp] = wpk;

    // L reduction: warp sums over its 32 positions for its 2 heads
    float v0 = w0, v1 = w1;
    #pragma unroll
    for (int o = 16; o; o >>= 1) {
        v0 += __shfl_xor_sync(0xffffffffu, v0, o);
        v1 += __shfl_xor_sync(0xffffffffu, v1, o);
    }
    int warp = t >> 5, lane = t & 31;
    if (lane == 0) { red[warp * 2 + 0] = v0; red[warp * 2 + 1] = v1; }
    __syncthreads();                // w4 + red visible
    if (t < 4) {
        int h2 = t >> 1, sub = t & 1;
        float L = red[(h2 * 4 + 0) * 2 + sub] + red[(h2 * 4 + 1) * 2 + sub]
                + red[(h2 * 4 + 2) * 2 + sub] + red[(h2 * 4 + 3) * 2 + sub];
        atomicAdd(&g_Lsum[b * NH + 2 * h2 + sub], L);
    }

    // ---- phase B: channel x position-half, conflict-free ----
    ull acc01 = 0, acc23 = 0;
    int c = -1, pbase = 0;
    if (t < 128)       { c = t & 63;        pbase = (t >> 6) * 64; }
    else if (t < 160)  { c = 64 + (t & 15); pbase = ((t >> 4) & 1) * 64; }

    if (t < 128) {
        #pragma unroll 4
        for (int j = 0; j < 64; j++) {
            int pp = pbase + j;
            float f = smem[pp * 64 + (c ^ ((pp & 15) << 2))];
            ull ff = pk2(f);
            ull w01, w23; ldsv2(w01, w23, w4b + pp * 16);
            fma2(acc01, ff, w01); fma2(acc23, ff, w23);
        }
    } else if (t < 160) {
        int cb = c - 64;
        #pragma unroll 4
        for (int j = 0; j < 64; j++) {
            int pp = pbase + j;
            float f = smem[8192 + pp * 16 + (cb ^ ((pp & 3) << 2))];
            ull ff = pk2(f);
            ull w01, w23; ldsv2(w01, w23, w4b + pp * 16);
            fma2(acc01, ff, w01); fma2(acc23, ff, w23);
        }
    }

    bool upper = (t >= 64 && t < 128) || (t >= 144 && t < 160);
    bool lower = (t < 64) || (t >= 128 && t < 144);
    if (upper) {
        float A0, A1, A2, A3;
        unpk(A0, A1, acc01); unpk(A2, A3, acc23);
        ((float4*)(smem + 10752))[c] = make_float4(A0, A1, A2, A3);
    }
    __syncthreads();
    if (lower) {
        float A0, A1, A2, A3;
        unpk(A0, A1, acc01); unpk(A2, A3, acc23);
        float4 m = ((float4*)(smem + 10752))[c];
        float* dst = &g_fsum[(b * FIN + c) * NH];
        atomicAdd(dst + 0, A0 + m.x);
        atomicAdd(dst + 1, A1 + m.y);
        atomicAdd(dst + 2, A2 + m.z);
        atomicAdd(dst + 3, A3 + m.w);
    }
}

// ---------------- K6: fused epilogue (PDL over k2) --------------------------
// grid (BB, 9), 256 threads. slice 0: Wv cp.async + extra copy pre-sync,
// then 4-way split GEMV. slices 1..8: mean_attn stream, 512 positions each.
__global__ void __launch_bounds__(256)
k6_out(const float* __restrict__ Wv, const float* __restrict__ bv,
       const float* __restrict__ extra, float* __restrict__ out,
       float* __restrict__ out_ma) {
    int b = blockIdx.x;
    int slice = blockIdx.y;
    int t = threadIdx.x;            // 256 threads
    __shared__ float linv[NH];
    __shared__ float wvsh[FIN * CF];      // 20 KB
    __shared__ float4 fbar4[FIN];
    __shared__ float parts[4][CF];

    if (slice == 0) {
        // pre-sync independent work: stage Wv, copy extra
        unsigned int wvb = (unsigned int)__cvta_generic_to_shared(wvsh);
        const float4* Wv4 = (const float4*)Wv;
        #pragma unroll
        for (int k = 0; k < 5; k++)
            cpasync16(wvb + (t + k * 256) * 16, Wv4 + t + k * 256);
        asm volatile("cp.async.commit_group;");
        out[b * 320 + 64 + t] = extra[b * 256 + t];

        cudaGridDependencySynchronize();       // wait k2 (atomics final)

        if (t < NH) linv[t] = 1.0f / g_Lsum[b * NH + t];
        float4 fs = make_float4(0.f, 0.f, 0.f, 0.f);
        if (t < FIN) fs = ((const float4*)g_fsum)[b * FIN + t];

        asm volatile("cp.async.wait_group 0;" ::: "memory");
        __syncthreads();

        if (t < FIN) {
            fs.x *= linv[0]; fs.y *= linv[1]; fs.z *= linv[2]; fs.w *= linv[3];
            fbar4[t] = fs;
        }
        __syncthreads();

        // 4-way split GEMV: j = output column, g = channel group of 20
        int j = t & 63, g = t >> 6;
        float acc = 0.f;
        #pragma unroll
        for (int cc = 0; cc < 20; cc++) {
            int c = g * 20 + cc;
            acc += wvsh[c * CF + j] * ((const float*)&fbar4[c])[j >> 4];
        }
        parts[g][j] = acc;
        __syncthreads();
        if (t < CF)
            out[b * 320 + t] = bv[t] + parts[0][t] + parts[1][t] + parts[2][t] + parts[3][t];
    } else {
        cudaGridDependencySynchronize();       // wait k2
        if (t < NH) linv[t] = 1.0f / g_Lsum[b * NH + t];
        __syncthreads();
        int p = (slice - 1) * 512 + t * 2;
        const float4* wf = (const float4*)g_wu;
        float4 w0 = wf[b * HW + p];
        float4 w1 = wf[b * HW + p + 1];
        float l0 = linv[0], l1 = linv[1], l2 = linv[2], l3 = linv[3];
        float v0 = 0.25f * (w0.x * l0 + w0.y * l1 + w0.z * l2 + w0.w * l3);
        float v1 = 0.25f * (w1.x * l0 + w1.y * l1 + w1.z * l2 + w1.w * l3);
        *(float2*)(out_ma + b * HW + p) = make_float2(v0, v1);
    }
}

// ---------------- launch ---------------------------------------------------
extern "C" void kernel_launch(void* const* d_in, const int* in_sizes, int n_in,
                              void* d_out, int out_size) {
    (void)in_sizes; (void)n_in; (void)out_size;
    const float* image = (const float*)d_in[0];
    const float* s1    = (const float*)d_in[1];
    const float* s2    = (const float*)d_in[2];
    const float* extra = (const float*)d_in[3];
    const float* Wq    = (const float*)d_in[4];
    const float* bq    = (const float*)d_in[5];
    const float* Wk    = (const float*)d_in[6];
    const float* bk    = (const float*)d_in[7];
    const float* Wv    = (const float*)d_in[8];
    const float* bv    = (const float*)d_in[9];
    const float* basis = (const float*)d_in[10];

    float* out    = (float*)d_out;                 // [B,320]
    float* out_ma = out + BB * 320;                // [B,64,64]

    cudaFuncSetAttribute(k2_main, cudaFuncAttributeMaxDynamicSharedMemorySize, K2_SMEM_BYTES);

    k1a_gemm<<<KSL, 256>>>(s1, s2, Wq);

    cudaLaunchAttribute at[1];
    at[0].id = cudaLaunchAttributeProgrammaticStreamSerialization;
    at[0].val.programmaticStreamSerializationAllowed = 1;

    cudaLaunchConfig_t cfg = {};
    cfg.attrs = at; cfg.numAttrs = 1; cfg.stream = 0;

    cfg.gridDim = dim3(BB); cfg.blockDim = dim3(512); cfg.dynamicSmemBytes = 0;
    cudaLaunchKernelEx(&cfg, k1b_query, bq, Wk, bk);

    cfg.gridDim = dim3(BB, NCH); cfg.blockDim = dim3(256); cfg.dynamicSmemBytes = K2_SMEM_BYTES;
    cudaLaunchKernelEx(&cfg, k2_main, image, basis);

    cfg.gridDim = dim3(BB, 9); cfg.blockDim = dim3(256); cfg.dynamicSmemBytes = 0;
    cudaLaunchKernelEx(&cfg, k6_out, Wv, bv, extra, out, out_ma);
}